// round 3
// baseline (speedup 1.0000x reference)
#include <cuda_runtime.h>

// ---------------------------------------------------------------------------
// TriplaneEncoding: N=2^20 points, 4 levels (r = 128,256,512,1024), C=4.
// out[i, l*12 + p*4 + c] = bilerp(plane[l][p][c], coords) * lineconst[l][p][c]
//                          * (1 - |x2[p]|/2)
// where lineconst = 0.5*(triline[.., r/2-1, 0] + triline[.., r/2, 0])
// (the line grid_sample degenerates because W=1 and the y-coordinate is 0).
// ---------------------------------------------------------------------------

// Transposed plane storage: per level, per plane: [y][x] -> float4 of channels.
// Level float4 offsets: 0, 3*128^2, +3*256^2, +3*512^2 ; total 4,177,920 float4.
__device__ float4 g_planes[4177920];
__device__ float4 g_lineconst[12];  // [level*3 + plane] -> 4 channels

// ---------------- transpose: (3,C,r,r) channel-major -> (3,r,r) float4 ------
__global__ void transpose_kernel(const float* __restrict__ src, int dst_off,
                                 int r, int sh) {
    int idx = blockIdx.x * blockDim.x + threadIdx.x;
    int total = 3 * r * r;
    if (idx >= total) return;
    int x = idx & (r - 1);
    int y = (idx >> sh) & (r - 1);
    int p = idx >> (2 * sh);
    int rr = r * r;
    const float* s = src + (size_t)(p * 4) * rr + y * r + x;
    float4 v;
    v.x = __ldg(s);
    v.y = __ldg(s + rr);
    v.z = __ldg(s + 2 * rr);
    v.w = __ldg(s + 3 * rr);
    g_planes[dst_off + idx] = v;
}

// ---------------- line constants -------------------------------------------
__global__ void lineconst_kernel(const float* __restrict__ t0,
                                 const float* __restrict__ t1,
                                 const float* __restrict__ t2,
                                 const float* __restrict__ t3) {
    int t = threadIdx.x;
    if (t >= 48) return;
    int l = t / 12;       // level
    int j = t % 12;       // p*4 + c
    const float* tl = (l == 0) ? t0 : (l == 1) ? t1 : (l == 2) ? t2 : t3;
    int r = 128 << l;
    float v = 0.5f * (__ldg(tl + j * r + r / 2 - 1) + __ldg(tl + j * r + r / 2));
    reinterpret_cast<float*>(g_lineconst)[t] = v;
}

// ---------------- main kernel ----------------------------------------------
__global__ __launch_bounds__(256) void tri_kernel(const float* __restrict__ xin,
                                                  float* __restrict__ out,
                                                  int N) {
    __shared__ float4 slc[12];
    if (threadIdx.x < 12) slc[threadIdx.x] = g_lineconst[threadIdx.x];
    __syncthreads();

    int i = blockIdx.x * blockDim.x + threadIdx.x;
    if (i >= N) return;

    float c0 = fmaf(__ldg(xin + 3 * i + 0), 2.f, -1.f);
    float c1 = fmaf(__ldg(xin + 3 * i + 1), 2.f, -1.f);
    float c2 = fmaf(__ldg(xin + 3 * i + 2), 2.f, -1.f);
    float c[3] = {c0, c1, c2};
    float wl[3];
#pragma unroll
    for (int d = 0; d < 3; d++) wl[d] = 1.f - 0.5f * fabsf(c[d]);

    float4* op = reinterpret_cast<float4*>(out) + (size_t)i * 12;

    int base = 0;
#pragma unroll
    for (int l = 0; l < 4; l++) {
        const int r = 128 << l;
        const int sh = 7 + l;
        const float hr = 0.5f * (float)r;

        // Per-axis coordinate prep (each axis feeds two planes).
        int i0[3], i1[3];
        float t0[3], t1[3];
#pragma unroll
        for (int d = 0; d < 3; d++) {
            float f = fmaf(c[d], hr, hr - 0.5f);
            float fl = floorf(f);
            float t = f - fl;
            int k = (int)fl;                // in [-1, r-1]
            bool v0 = (k >= 0);
            bool v1 = (k < r - 1);
            t0[d] = v0 ? (1.f - t) : 0.f;   // zero-padding semantics
            t1[d] = v1 ? t : 0.f;
            i0[d] = v0 ? k : 0;             // clamped, weight already zeroed
            i1[d] = v1 ? (k + 1) : (r - 1);
        }

#pragma unroll
        for (int p = 0; p < 3; p++) {
            const int ua = p;               // u (width) axis of plane p
            const int va = (p + 2) % 3;     // v (height) axis: {2,0,1}
            const float4* pl = g_planes + base + p * r * r;
            int r0 = i0[va] << sh;
            int r1 = i1[va] << sh;
            float4 v00 = __ldg(pl + r0 + i0[ua]);
            float4 v10 = __ldg(pl + r0 + i1[ua]);
            float4 v01 = __ldg(pl + r1 + i0[ua]);
            float4 v11 = __ldg(pl + r1 + i1[ua]);
            float w00 = t0[ua] * t0[va];
            float w10 = t1[ua] * t0[va];
            float w01 = t0[ua] * t1[va];
            float w11 = t1[ua] * t1[va];
            float4 lc = slc[l * 3 + p];
            float s = wl[p];
            float4 o;
            o.x = (w00 * v00.x + w10 * v10.x + w01 * v01.x + w11 * v11.x) * (lc.x * s);
            o.y = (w00 * v00.y + w10 * v10.y + w01 * v01.y + w11 * v11.y) * (lc.y * s);
            o.z = (w00 * v00.z + w10 * v10.z + w01 * v01.z + w11 * v11.z) * (lc.z * s);
            o.w = (w00 * v00.w + w10 * v10.w + w01 * v01.w + w11 * v11.w) * (lc.w * s);
            op[l * 3 + p] = o;
        }
        base += 3 * r * r;
    }
}

// ---------------------------------------------------------------------------
extern "C" void kernel_launch(void* const* d_in, const int* in_sizes, int n_in,
                              void* d_out, int out_size) {
    const float* x = (const float*)d_in[0];
    const float* tp[4] = {nullptr, nullptr, nullptr, nullptr};
    const float* tl[4] = {nullptr, nullptr, nullptr, nullptr};

    // Resolve inputs by element count (robust to metadata ordering).
    for (int i = 1; i < n_in; i++) {
        int s = in_sizes[i];
        const float* ptr = (const float*)d_in[i];
        switch (s) {
            case 12 * 128 * 128:   tp[0] = ptr; break;
            case 12 * 256 * 256:   tp[1] = ptr; break;
            case 12 * 512 * 512:   tp[2] = ptr; break;
            case 12 * 1024 * 1024: tp[3] = ptr; break;
            case 12 * 128:         tl[0] = ptr; break;
            case 12 * 256:         tl[1] = ptr; break;
            case 12 * 512:         tl[2] = ptr; break;
            case 12 * 1024:        tl[3] = ptr; break;
            default: break;
        }
    }

    int N = in_sizes[0] / 3;

    // 1) transpose planes into channel-last float4 layout
    int offs[4] = {0, 3 * 128 * 128, 3 * 128 * 128 + 3 * 256 * 256,
                   3 * 128 * 128 + 3 * 256 * 256 + 3 * 512 * 512};
    for (int l = 0; l < 4; l++) {
        int r = 128 << l;
        int total = 3 * r * r;
        transpose_kernel<<<(total + 255) / 256, 256>>>(tp[l], offs[l], r, 7 + l);
    }

    // 2) line constants
    lineconst_kernel<<<1, 64>>>(tl[0], tl[1], tl[2], tl[3]);

    // 3) main gather kernel
    tri_kernel<<<(N + 255) / 256, 256>>>(x, (float*)d_out, N);
}

// round 6
// speedup vs baseline: 1.0157x; 1.0157x over previous
#include <cuda_runtime.h>
#include <cuda_fp16.h>
#include <math.h>

// ---------------------------------------------------------------------------
// TriplaneEncoding, N=2^20 pts, levels r=128..1024, C=4.
// Line branch degenerates to per-(level,plane,channel) constants times
// (1 - |x2[p]|/2).  Planes are re-stored as fp16 half4 texels in HORIZONTAL
// PAIRS at both parities:
//   even block: pair k=2j   -> (T[2j],   T[2j+1]),  j=0..r/2-1
//   odd  block: pair k=2j-1 -> (T[2j-1], T[2j]),    j=0..r/2  (zero pads at
//                              k=-1 first slot and k=r-1 last slot)
// One LDG.128 fetches both u-corners (all 4 channels) for one row: 2 gathers
// per plane, 24 per point (was 48).
// Layout per (level l, plane p): [even: r * r/2 uint4][odd: r * (r/2+1) uint4]
// Level bases (uint4 units): 0, 49536, 246912, 1034880; total 4,183,680 (67MB)
// ---------------------------------------------------------------------------

__device__ uint4  g_planes[4183680];
__device__ float4 g_lineconst[12];

__device__ __forceinline__ __half2 h2(unsigned u) {
    union { unsigned u; __half2 h; } cv; cv.u = u; return cv.h;
}
__device__ __forceinline__ unsigned u32(__half2 h) {
    union { unsigned u; __half2 h; } cv; cv.h = h; return cv.u;
}

// ---------------- convert: (3,C,r,r) fp32 -> dual-parity half4 pairs --------
__global__ __launch_bounds__(256) void convert_kernel(
    const float* __restrict__ p0, const float* __restrict__ p1,
    const float* __restrict__ p2, const float* __restrict__ p3) {
    const int LB[4] = {0, 49536, 246912, 1034880};
    int l = blockIdx.y;
    int r = 128 << l;
    int per = r * (r + 1);            // uint4 units per plane (even+odd)
    int total = 3 * per;
    int idx = blockIdx.x * 256 + threadIdx.x;
    if (idx >= total) return;
    const float* src = (l == 0) ? p0 : (l == 1) ? p1 : (l == 2) ? p2 : p3;

    int p = idx / per;
    int rem = idx - p * per;
    int eCnt = r * (r >> 1);
    int y, k;
    if (rem < eCnt) {                 // even block
        y = rem >> (6 + l);           // / (r/2)
        int j = rem & ((r >> 1) - 1);
        k = 2 * j;
    } else {                          // odd block
        int rr = rem - eCnt;
        int s = (r >> 1) + 1;
        y = rr / s;
        int j = rr - y * s;
        k = 2 * j - 1;                // -1 .. r-1
    }

    int rr2 = r * r;
    const float* rb = src + (size_t)p * 4 * rr2 + (size_t)y * r;
    float v0[4] = {0.f, 0.f, 0.f, 0.f};
    float v1[4] = {0.f, 0.f, 0.f, 0.f};
    if (k >= 0) {
#pragma unroll
        for (int c = 0; c < 4; c++) v0[c] = __ldg(rb + c * rr2 + k);
    }
    if (k + 1 < r) {
#pragma unroll
        for (int c = 0; c < 4; c++) v1[c] = __ldg(rb + c * rr2 + k + 1);
    }
    uint4 o;
    o.x = u32(__floats2half2_rn(v0[0], v0[1]));
    o.y = u32(__floats2half2_rn(v0[2], v0[3]));
    o.z = u32(__floats2half2_rn(v1[0], v1[1]));
    o.w = u32(__floats2half2_rn(v1[2], v1[3]));
    g_planes[LB[l] + p * per + rem] = o;
}

// ---------------- line constants -------------------------------------------
__global__ void lineconst_kernel(const float* __restrict__ t0,
                                 const float* __restrict__ t1,
                                 const float* __restrict__ t2,
                                 const float* __restrict__ t3) {
    int t = threadIdx.x;
    if (t >= 48) return;
    int l = t / 12;
    int j = t % 12;
    const float* tl = (l == 0) ? t0 : (l == 1) ? t1 : (l == 2) ? t2 : t3;
    int r = 128 << l;
    float v = 0.5f * (__ldg(tl + j * r + r / 2 - 1) + __ldg(tl + j * r + r / 2));
    reinterpret_cast<float*>(g_lineconst)[t] = v;
}

// ---------------- main kernel ----------------------------------------------
__global__ __launch_bounds__(256) void tri_kernel(const float* __restrict__ xin,
                                                  float* __restrict__ out,
                                                  int N) {
    __shared__ float4 slc[12];
    if (threadIdx.x < 12) slc[threadIdx.x] = g_lineconst[threadIdx.x];
    __syncthreads();

    int i = blockIdx.x * 256 + threadIdx.x;
    if (i >= N) return;

    float c[3], wl[3];
#pragma unroll
    for (int d = 0; d < 3; d++) {
        c[d] = fmaf(__ldg(xin + 3 * i + d), 2.f, -1.f);
        wl[d] = 1.f - 0.5f * fabsf(c[d]);
    }

    float4* op = reinterpret_cast<float4*>(out) + (size_t)i * 12;
    const int LB[4] = {0, 49536, 246912, 1034880};

#pragma unroll
    for (int l = 0; l < 4; l++) {
        const int r = 128 << l;
        const float hr = 0.5f * (float)r;

        int baseu[3], strideu[3], y0[3], y1[3];
        __half2 tuh[3], ty0h[3], ty1h[3];
#pragma unroll
        for (int d = 0; d < 3; d++) {
            float f = fmaf(c[d], hr, hr - 0.5f);
            float fl = floorf(f);
            float t = f - fl;
            int k = (int)fl;                    // in [-1, r-1]
            int par = k & 1;
            int col = (k + par) >> 1;
            strideu[d] = (r >> 1) + par;
            int eb = LB[l] + d * r * (r + 1);   // plane d: u-axis is axis d
            baseu[d] = (par ? (eb + r * (r >> 1)) : eb) + col;
            tuh[d] = __float2half2_rn(t);
            y0[d] = max(k, 0);
            y1[d] = min(k + 1, r - 1);
            // axis d is v-axis of plane (d+1)%3; fold its line weight in
            float s = wl[(d + 1) % 3];
            float w0 = (k >= 0) ? (1.f - t) * s : 0.f;   // zero-padding mask
            float w1 = (k < r - 1) ? t * s : 0.f;
            ty0h[d] = __float2half2_rn(w0);
            ty1h[d] = __float2half2_rn(w1);
        }

#pragma unroll
        for (int p = 0; p < 3; p++) {
            const int ua = p;
            const int va = (p + 2) % 3;
            const uint4* q = g_planes + baseu[ua];
            int st = strideu[ua];
            uint4 A = __ldg(q + y0[va] * st);   // row y0: (T0 | T1) half4 pair
            uint4 B = __ldg(q + y1[va] * st);   // row y1
            __half2 tu = tuh[ua];
            // x-lerp in fp16: v0 + t*(v1-v0)
            __half2 xl0a = __hfma2(tu, __hsub2(h2(A.z), h2(A.x)), h2(A.x));
            __half2 xl0b = __hfma2(tu, __hsub2(h2(A.w), h2(A.y)), h2(A.y));
            __half2 xl1a = __hfma2(tu, __hsub2(h2(B.z), h2(B.x)), h2(B.x));
            __half2 xl1b = __hfma2(tu, __hsub2(h2(B.w), h2(B.y)), h2(B.y));
            // y-lerp in fp16 (weights carry line-scale s)
            __half2 yla = __hfma2(ty1h[va], xl1a, __hmul2(ty0h[va], xl0a));
            __half2 ylb = __hfma2(ty1h[va], xl1b, __hmul2(ty0h[va], xl0b));
            float2 fa = __half22float2(yla);
            float2 fb = __half22float2(ylb);
            float4 lc = slc[l * 3 + p];
            float4 o;
            o.x = fa.x * lc.x;
            o.y = fa.y * lc.y;
            o.z = fb.x * lc.z;
            o.w = fb.y * lc.w;
            op[l * 3 + p] = o;
        }
    }
}

// ---------------------------------------------------------------------------
extern "C" void kernel_launch(void* const* d_in, const int* in_sizes, int n_in,
                              void* d_out, int out_size) {
    const float* x = (const float*)d_in[0];
    const float* tp[4] = {nullptr, nullptr, nullptr, nullptr};
    const float* tl[4] = {nullptr, nullptr, nullptr, nullptr};

    for (int i = 1; i < n_in; i++) {
        int s = in_sizes[i];
        const float* ptr = (const float*)d_in[i];
        switch (s) {
            case 12 * 128 * 128:   tp[0] = ptr; break;
            case 12 * 256 * 256:   tp[1] = ptr; break;
            case 12 * 512 * 512:   tp[2] = ptr; break;
            case 12 * 1024 * 1024: tp[3] = ptr; break;
            case 12 * 128:         tl[0] = ptr; break;
            case 12 * 256:         tl[1] = ptr; break;
            case 12 * 512:         tl[2] = ptr; break;
            case 12 * 1024:        tl[3] = ptr; break;
            default: break;
        }
    }

    int N = in_sizes[0] / 3;

    // 1) one-launch convert into dual-parity fp16 pair layout
    int max_units = 3 * 1024 * 1025;                 // largest level
    dim3 cgrid((max_units + 255) / 256, 4);
    convert_kernel<<<cgrid, 256>>>(tp[0], tp[1], tp[2], tp[3]);

    // 2) line constants
    lineconst_kernel<<<1, 64>>>(tl[0], tl[1], tl[2], tl[3]);

    // 3) main gather kernel
    tri_kernel<<<(N + 255) / 256, 256>>>(x, (float*)d_out, N);
}